// round 1
// baseline (speedup 1.0000x reference)
#include <cuda_runtime.h>

// CustomLinearRNN: h_t = A4 h_{t-1} + A3 x_t ; known_t = A1 x_t + A2 h_{t-1}
// x: [T,K,B] f32, init_hidden: [H,B], A1:[K,K], A2:[K,H], A3:[H,K], A4:[H,H]
// out: known_seq [T,K,B] followed by hidden_seq [T,H,B]  (f32)
//
// Strategy: one CTA per batch column b (columns are independent chains).
// Combined weight matrix W[192][192]: rows 0..127 -> h rows ([A3 | A4]),
// rows 128..191 -> known rows ([A1 | A2]). v[192] = [x_t(64) ; h_{t-1}(128)].
// Weights are register-resident (72 per thread), v broadcast from smem,
// partial sums reduced through smem. x_{t+1} prefetched during compute.

#define T_STEPS 4096
#define KDIM 64
#define HDIM 128
#define BDIM 128
#define NROWS 192
#define NV 192
#define NTHREADS 512
#define NI 6    // rows per thread
#define NJ 12   // j-columns per thread
#define NJG 16  // j groups (= NV / NJ)
#define PARTW 17

__global__ __launch_bounds__(NTHREADS, 1)
void rnn_seq_kernel(const float* __restrict__ x,
                    const float* __restrict__ h0,
                    const float* __restrict__ A1,
                    const float* __restrict__ A2,
                    const float* __restrict__ A3,
                    const float* __restrict__ A4,
                    float* __restrict__ out_known,
                    float* __restrict__ out_hidden)
{
    __shared__ __align__(16) float v[NV];
    __shared__ float part[NROWS * PARTW];

    const int b   = blockIdx.x;
    const int tid = threadIdx.x;
    const int rg  = tid & 31;    // lane = row group -> v loads broadcast per warp
    const int jg  = tid >> 5;    // warp = j group
    const int row0 = rg * NI;
    const int j0   = jg * NJ;

    // ---- load register-resident weights (once) ----
    float w[NI][NJ];
    #pragma unroll
    for (int r = 0; r < NI; r++) {
        const int R = row0 + r;
        #pragma unroll
        for (int jj = 0; jj < NJ; jj++) {
            const int J = j0 + jj;
            float wv;
            if (R < HDIM) {
                wv = (J < KDIM) ? A3[R * KDIM + J]
                                : A4[R * HDIM + (J - KDIM)];
            } else {
                const int i = R - HDIM;
                wv = (J < KDIM) ? A1[i * KDIM + J]
                                : A2[i * HDIM + (J - KDIM)];
            }
            w[r][jj] = wv;
        }
    }

    // ---- init v = [x_0 ; h_init] ----
    if (tid < KDIM)                 v[tid] = x[tid * BDIM + b];
    if (tid >= 64 && tid < 64+HDIM) v[tid] = h0[(tid - 64) * BDIM + b];
    __syncthreads();

    #pragma unroll 1
    for (int t = 0; t < T_STEPS; t++) {
        // prefetch x_{t+1} (latency overlaps the FMA block below)
        float xr = 0.0f;
        if (tid >= 256 && tid < 256 + KDIM && (t + 1) < T_STEPS)
            xr = x[((size_t)(t + 1) * KDIM + (tid - 256)) * BDIM + b];

        // read this thread's 12 v values (float4 broadcasts within warp)
        float vv[NJ];
        {
            const float4* v4 = reinterpret_cast<const float4*>(v);
            float4 p0 = v4[jg * 3 + 0];
            float4 p1 = v4[jg * 3 + 1];
            float4 p2 = v4[jg * 3 + 2];
            vv[0]=p0.x; vv[1]=p0.y; vv[2]=p0.z;  vv[3]=p0.w;
            vv[4]=p1.x; vv[5]=p1.y; vv[6]=p1.z;  vv[7]=p1.w;
            vv[8]=p2.x; vv[9]=p2.y; vv[10]=p2.z; vv[11]=p2.w;
        }

        // 72 FMAs, 6 independent accumulator chains
        float acc[NI];
        #pragma unroll
        for (int r = 0; r < NI; r++) {
            float s0 = w[r][0] * vv[0];
            float s1 = w[r][1] * vv[1];
            float s2 = w[r][2] * vv[2];
            float s3 = w[r][3] * vv[3];
            #pragma unroll
            for (int jj = 4; jj < NJ; jj += 4) {
                s0 = fmaf(w[r][jj+0], vv[jj+0], s0);
                s1 = fmaf(w[r][jj+1], vv[jj+1], s1);
                s2 = fmaf(w[r][jj+2], vv[jj+2], s2);
                s3 = fmaf(w[r][jj+3], vv[jj+3], s3);
            }
            acc[r] = (s0 + s1) + (s2 + s3);
        }

        // store partials
        #pragma unroll
        for (int r = 0; r < NI; r++)
            part[(row0 + r) * PARTW + jg] = acc[r];
        __syncthreads();

        // reduce 16 partials per output row; update v (h) and write outputs
        if (tid < NROWS) {
            const float* p = &part[tid * PARTW];
            float s0 = p[0] + p[1];
            float s1 = p[2] + p[3];
            float s2 = p[4] + p[5];
            float s3 = p[6] + p[7];
            s0 += p[8]  + p[9];
            s1 += p[10] + p[11];
            s2 += p[12] + p[13];
            s3 += p[14] + p[15];
            const float s = (s0 + s1) + (s2 + s3);
            if (tid < HDIM) {
                v[64 + tid] = s;  // h_t for next step
                out_hidden[(size_t)t * (HDIM * BDIM) + tid * BDIM + b] = s;
            } else {
                out_known[(size_t)t * (KDIM * BDIM) + (tid - HDIM) * BDIM + b] = s;
            }
        }
        // install prefetched x_{t+1}
        if (tid >= 256 && tid < 256 + KDIM)
            v[tid - 256] = xr;
        __syncthreads();
    }
}

extern "C" void kernel_launch(void* const* d_in, const int* in_sizes, int n_in,
                              void* d_out, int out_size)
{
    const float* x  = (const float*)d_in[0];  // [T,K,B]
    const float* h0 = (const float*)d_in[1];  // [H,B]
    const float* A1 = (const float*)d_in[2];  // [K,K]
    const float* A2 = (const float*)d_in[3];  // [K,H]
    const float* A3 = (const float*)d_in[4];  // [H,K]
    const float* A4 = (const float*)d_in[5];  // [H,H]

    float* out_known  = (float*)d_out;                                   // [T,K,B]
    float* out_hidden = (float*)d_out + (size_t)T_STEPS * KDIM * BDIM;   // [T,H,B]

    rnn_seq_kernel<<<BDIM, NTHREADS>>>(x, h0, A1, A2, A3, A4,
                                       out_known, out_hidden);
    (void)in_sizes; (void)n_in; (void)out_size;
}